// round 15
// baseline (speedup 1.0000x reference)
#include <cuda_runtime.h>
#include <cuda_fp16.h>
#include <cstdint>

#define D 128
#define MAX_N 100000
#define MAX_E 3200000
#define BINSZ 96              // fixed per-node bucket (deg ~ Poisson(32); 96 = +11 sigma)
#define MAX_SPILL 2048
#define BM 32                 // rows per group
#define GROUPS 8              // row-groups per block (256 rows/block)

// ---------------------------------------------------------------------------
// Static device scratch
// ---------------------------------------------------------------------------
__device__ int    g_is64;
__device__ int    g_cnt [MAX_N];                   // atomic degree counters
__device__ int    g_bins[(size_t)MAX_N * BINSZ];   // src ids, fixed stride
__device__ int    g_spillcnt;
__device__ int2   g_spill[MAX_SPILL];              // (src, dst) overflow edges
__device__ float  g_dis [MAX_N];                   // (deg+1)^-1/2
__device__ __half g_wh  [D * D];                   // W fp16
__device__ __half g_hp  [(size_t)MAX_N * D];       // (x @ W^T) * dis[row], fp16

// ---------------------------------------------------------------------------
// 1. prep: zero counters + detect edge dtype + convert W to fp16
// ---------------------------------------------------------------------------
__global__ void prep_kernel(const float* __restrict__ w, const int* __restrict__ p, int n) {
    int gid = blockIdx.x * blockDim.x + threadIdx.x;
    if (gid < n) g_cnt[gid] = 0;
    if (gid == 0) g_spillcnt = 0;
    if (gid < D * D / 2) {
        float2 v = ((const float2*)w)[gid];
        ((__half2*)g_wh)[gid] = __floats2half2_rn(v.x, v.y);
    }
    if (blockIdx.x == 0) {
        __shared__ int any;
        if (threadIdx.x == 0) any = 0;
        __syncthreads();
        int v = 0;
        for (int i = threadIdx.x; i < 2048; i += blockDim.x) v |= p[2 * i + 1];
        if (v) atomicOr(&any, 1);
        __syncthreads();
        if (threadIdx.x == 0) g_is64 = (any == 0) ? 1 : 0;
    }
}

// ---------------------------------------------------------------------------
// 2. fill: single edge pass builds binned adjacency + degree counts
// ---------------------------------------------------------------------------
__device__ __forceinline__ void fill_one(int s, int d, int n) {
    if ((unsigned)d < (unsigned)n) {
        if ((unsigned)s >= (unsigned)n) s = 0;
        int pos = atomicAdd(&g_cnt[d], 1);
        if (pos < BINSZ) {
            g_bins[(size_t)d * BINSZ + pos] = s;
        } else {
            int sp = atomicAdd(&g_spillcnt, 1);
            if (sp < MAX_SPILL) g_spill[sp] = make_int2(s, d);
        }
    }
}

__global__ void fill_kernel(const int* __restrict__ p, int e, int n) {
    int gid = blockIdx.x * blockDim.x + threadIdx.x;
    int stride = gridDim.x * blockDim.x;
    if (!g_is64) {
        const int4* s4 = (const int4*)p;
        const int4* d4 = (const int4*)(p + e);
        int e4 = e >> 2;
        for (int i = gid; i < e4; i += stride) {
            int4 sv = s4[i];
            int4 dv = d4[i];
            fill_one(sv.x, dv.x, n);
            fill_one(sv.y, dv.y, n);
            fill_one(sv.z, dv.z, n);
            fill_one(sv.w, dv.w, n);
        }
        if (gid < (e & 3)) {
            int i = (e & ~3) + gid;
            fill_one(p[i], p[(size_t)e + i], n);
        }
    } else {
        for (int i = gid; i < e; i += stride) {
            int s = p[2 * (size_t)i];
            int d = p[2 * ((size_t)e + i)];
            fill_one(s, d, n);
        }
    }
}

// ---------------------------------------------------------------------------
// 3. dis = rsqrt(deg + 1)
// ---------------------------------------------------------------------------
__global__ void dis_kernel(int n) {
    int i = blockIdx.x * blockDim.x + threadIdx.x;
    if (i < n) g_dis[i] = rsqrtf((float)(g_cnt[i] + 1));
}

// ---------------------------------------------------------------------------
// 4. tensor-core GEMM: A fragments loaded DIRECTLY from global (no A smem,
//    no in-loop syncs). W staged to smem once/block; B frags resident in regs.
//    Block: 256 thr (8 warps), 8 groups x 32 rows = 256 rows.
//    Warp w: rows 16*(w&1), cols 32*(w>>1). A k-chunks software-pipelined.
// ---------------------------------------------------------------------------
__global__ __launch_bounds__(256, 2) void gemm_mma_kernel(
    const float* __restrict__ x, int n)
{
    __shared__ __half sw[D][136];          // W staged once per block

    const int t = threadIdx.x;
    const int wid = t >> 5, lane = t & 31;
    const int blockRow0 = blockIdx.x * (BM * GROUPS);
    const int mrow0 = (wid & 1) * 16;
    const int ncol0 = (wid >> 1) * 32;
    const int g4 = lane >> 2, tig = lane & 3;    // fragment row/col within tile

    float2 af[2][4];

    // A fragment loader: m16n8k16 A layout, rows (g4, g4+8), cols (2*tig, +8)
    auto loadA = [&](int g, int k0, float2* dst) {
        int r0 = blockRow0 + g * BM + mrow0 + g4;
        int r1 = r0 + 8;
        int c0 = k0 * 16 + tig * 2;
        const float* xr0 = x + (size_t)r0 * D + c0;
        const float* xr1 = x + (size_t)r1 * D + c0;
        bool v0 = r0 < n, v1 = r1 < n;
        dst[0] = v0 ? *(const float2*)(xr0)     : make_float2(0.f, 0.f);
        dst[1] = v1 ? *(const float2*)(xr1)     : make_float2(0.f, 0.f);
        dst[2] = v0 ? *(const float2*)(xr0 + 8) : make_float2(0.f, 0.f);
        dst[3] = v1 ? *(const float2*)(xr1 + 8) : make_float2(0.f, 0.f);
    };

    // prime the pipeline before the W stage (overlaps DRAM latency with staging)
    loadA(0, 0, af[0]);

    // stage W (each thread: one half-row segment of 64 cols = 8 uint4)
    {
        int r = t >> 1, cseg = (t & 1) * 64;
        const uint4* wp = (const uint4*)(g_wh + r * D + cseg);
#pragma unroll
        for (int q = 0; q < 8; q++)
            *(uint4*)&sw[r][cseg + 8 * q] = wp[q];
    }
    __syncthreads();

    // load all B fragments into registers: 8 k-chunks x 4 n-tiles x 2 regs
    const int brow = lane & 7;
    const int bcol = ((lane >> 3) & 1) * 8;
    uint32_t bf[8][4][2];
#pragma unroll
    for (int k0 = 0; k0 < 8; k0++) {
#pragma unroll
        for (int nt = 0; nt < 4; nt++) {
            unsigned baddr = (unsigned)__cvta_generic_to_shared(
                &sw[ncol0 + nt * 8 + brow][k0 * 16 + bcol]);
            asm volatile("ldmatrix.sync.aligned.m8n8.x2.shared.b16 {%0,%1}, [%2];"
                         : "=r"(bf[k0][nt][0]), "=r"(bf[k0][nt][1]) : "r"(baddr));
        }
    }

    __half2* hp2 = (__half2*)g_hp;

    for (int g = 0; g < GROUPS; g++) {
        const int row0 = blockRow0 + g * BM;
        if (row0 >= n) break;

        float acc[4][4];
#pragma unroll
        for (int i = 0; i < 4; i++) { acc[i][0]=0.f; acc[i][1]=0.f; acc[i][2]=0.f; acc[i][3]=0.f; }

#pragma unroll
        for (int k0 = 0; k0 < 8; k0++) {
            // prefetch next chunk (or next group's chunk 0)
            int nk = k0 + 1, ng = g;
            if (nk == 8) { nk = 0; ng = g + 1; }
            if (ng < GROUPS) loadA(ng, nk, af[(k0 + 1) & 1]);

            // convert current chunk to half2 fragment regs
            const float2* a = af[k0 & 1];
            uint32_t ar[4];
            __half2 h;
            h = __floats2half2_rn(a[0].x, a[0].y); ar[0] = *reinterpret_cast<uint32_t*>(&h);
            h = __floats2half2_rn(a[1].x, a[1].y); ar[1] = *reinterpret_cast<uint32_t*>(&h);
            h = __floats2half2_rn(a[2].x, a[2].y); ar[2] = *reinterpret_cast<uint32_t*>(&h);
            h = __floats2half2_rn(a[3].x, a[3].y); ar[3] = *reinterpret_cast<uint32_t*>(&h);

#pragma unroll
            for (int nt = 0; nt < 4; nt++) {
                asm volatile("mma.sync.aligned.m16n8k16.row.col.f32.f16.f16.f32 "
                             "{%0,%1,%2,%3}, {%4,%5,%6,%7}, {%8,%9}, {%0,%1,%2,%3};"
                             : "+f"(acc[nt][0]), "+f"(acc[nt][1]),
                               "+f"(acc[nt][2]), "+f"(acc[nt][3])
                             : "r"(ar[0]), "r"(ar[1]), "r"(ar[2]), "r"(ar[3]),
                               "r"(bf[k0][nt][0]), "r"(bf[k0][nt][1]));
            }
        }

        // epilogue: scale by dis[row], convert to fp16, store
        const int r0e = row0 + mrow0 + g4;
        const int r1e = r0e + 8;
        float s0 = (r0e < n) ? g_dis[r0e] : 0.f;
        float s1 = (r1e < n) ? g_dis[r1e] : 0.f;
#pragma unroll
        for (int nt = 0; nt < 4; nt++) {
            int c = ncol0 + nt * 8 + 2 * tig;
            if (r0e < n) hp2[(size_t)r0e * 64 + (c >> 1)] = __floats2half2_rn(acc[nt][0] * s0, acc[nt][1] * s0);
            if (r1e < n) hp2[(size_t)r1e * 64 + (c >> 1)] = __floats2half2_rn(acc[nt][2] * s1, acc[nt][3] * s1);
        }
    }
}

// ---------------------------------------------------------------------------
// 5. gather-aggregate: one warp per node, two edges per iteration.
// ---------------------------------------------------------------------------
__device__ __forceinline__ void add8(float* a, uint4 v) {
    float2 f;
    f = __half22float2(*(__half2*)&v.x); a[0] += f.x; a[1] += f.y;
    f = __half22float2(*(__half2*)&v.y); a[2] += f.x; a[3] += f.y;
    f = __half22float2(*(__half2*)&v.z); a[4] += f.x; a[5] += f.y;
    f = __half22float2(*(__half2*)&v.w); a[6] += f.x; a[7] += f.y;
}

__global__ __launch_bounds__(256) void aggregate_kernel(
    const float* __restrict__ bias, float* __restrict__ out, int n)
{
    int node = (blockIdx.x * blockDim.x + threadIdx.x) >> 5;
    int lane = threadIdx.x & 31;
    if (node >= n) return;
    const int half_id = lane >> 4;
    const int sub = lane & 15;

    const uint4* hp16 = (const uint4*)g_hp;
    const int start = node * BINSZ;
    int k = g_cnt[node];
    if (k > BINSZ) k = BINSZ;

    float acc[8] = {0.f, 0.f, 0.f, 0.f, 0.f, 0.f, 0.f, 0.f};
    if (half_id == 0) add8(acc, hp16[(size_t)node * 16 + sub]);   // self loop

    int j = 0;
    int full = k & ~31;
    for (; j < full; j += 32) {
        int my = g_bins[start + j + lane];
#pragma unroll
        for (int t2 = 0; t2 < 16; t2++) {
            int s = __shfl_sync(0xFFFFFFFFu, my, 2 * t2 + half_id);
            add8(acc, hp16[(size_t)s * 16 + sub]);
        }
    }
    int m = k - j;
    if (m > 0) {
        int idx = j + lane;
        int my = (idx < k) ? g_bins[start + idx] : 0;
        int pairs = m >> 1;
        for (int t2 = 0; t2 < pairs; t2++) {
            int s = __shfl_sync(0xFFFFFFFFu, my, 2 * t2 + half_id);
            add8(acc, hp16[(size_t)s * 16 + sub]);
        }
        if (m & 1) {
            int s = __shfl_sync(0xFFFFFFFFu, my, m - 1);
            if (half_id == 0) add8(acc, hp16[(size_t)s * 16 + sub]);
        }
    }

#pragma unroll
    for (int i = 0; i < 8; i++)
        acc[i] += __shfl_down_sync(0xFFFFFFFFu, acc[i], 16);

    if (half_id == 0) {
        float sd = g_dis[node];
        const float4* b4 = (const float4*)bias;
        float4 ba = b4[sub * 2], bb = b4[sub * 2 + 1];
        float4 o0, o1;
        o0.x = fmaf(sd, acc[0], ba.x);
        o0.y = fmaf(sd, acc[1], ba.y);
        o0.z = fmaf(sd, acc[2], ba.z);
        o0.w = fmaf(sd, acc[3], ba.w);
        o1.x = fmaf(sd, acc[4], bb.x);
        o1.y = fmaf(sd, acc[5], bb.y);
        o1.z = fmaf(sd, acc[6], bb.z);
        o1.w = fmaf(sd, acc[7], bb.w);
        float4* op = (float4*)out + (size_t)node * 32 + sub * 2;
        op[0] = o0;
        op[1] = o1;
    }
}

// ---------------------------------------------------------------------------
// 6. spill fixup (normally zero work)
// ---------------------------------------------------------------------------
__global__ void spill_kernel(float* __restrict__ out) {
    int nsp = g_spillcnt;
    if (nsp > MAX_SPILL) nsp = MAX_SPILL;
    int warp = (blockIdx.x * blockDim.x + threadIdx.x) >> 5;
    int lane = threadIdx.x & 31;
    int wstride = (gridDim.x * blockDim.x) >> 5;
    for (int i = warp; i < nsp; i += wstride) {
        int2 ed = g_spill[i];
        float sd = g_dis[ed.y];
        uint2 v = ((const uint2*)g_hp)[(size_t)ed.x * 32 + lane];
        float2 f0 = __half22float2(*(__half2*)&v.x);
        float2 f1 = __half22float2(*(__half2*)&v.y);
        float* o = out + (size_t)ed.y * D + lane * 4;
        atomicAdd(o + 0, sd * f0.x);
        atomicAdd(o + 1, sd * f0.y);
        atomicAdd(o + 2, sd * f1.x);
        atomicAdd(o + 3, sd * f1.y);
    }
}

// ---------------------------------------------------------------------------
// 7. zero any padding tail of d_out
// ---------------------------------------------------------------------------
__global__ void zero_tail_kernel(float* out, int begin, int end) {
    int i = begin + blockIdx.x * blockDim.x + threadIdx.x;
    if (i < end) out[i] = 0.f;
}

// ---------------------------------------------------------------------------
extern "C" void kernel_launch(void* const* d_in, const int* in_sizes, int n_in,
                              void* d_out, int out_size) {
    const float* x    = (const float*)d_in[0];
    const int*   ei   = (const int*)d_in[1];
    const float* w    = (const float*)d_in[2];
    const float* bias = (const float*)d_in[3];
    float*       out  = (float*)d_out;

    const int n = in_sizes[0] / D;     // 100000
    const int e = in_sizes[1] / 2;     // 3200000

    // 1. zero counters + dtype detect + W conversion (fused)
    prep_kernel<<<(n + 255) / 256, 256>>>(w, ei, n);

    // 2. single edge pass: binned adjacency + degrees
    fill_kernel<<<2048, 256>>>(ei, e, n);

    // 3. dis = rsqrt(deg + 1)
    dis_kernel<<<(n + 255) / 256, 256>>>(n);

    // 4. tensor-core dense transform (256 rows per block, direct-LDG A)
    {
        int rows_per_block = BM * GROUPS;
        gemm_mma_kernel<<<(n + rows_per_block - 1) / rows_per_block, 256>>>(x, n);
    }

    // 5. gather aggregation with fused finalize
    {
        long long total_threads = (long long)n * 32;
        int blocks = (int)((total_threads + 255) / 256);
        aggregate_kernel<<<blocks, 256>>>(bias, out, n);
    }

    // 6. spill fixup (no-op unless a node exceeded BINSZ)
    spill_kernel<<<64, 256>>>(out);

    // 7. padding tail, if any
    if (out_size > n * D) {
        int extra = out_size - n * D;
        zero_tail_kernel<<<(extra + 255) / 256, 256>>>(out, n * D, out_size);
    }
}

// round 16
// speedup vs baseline: 1.6026x; 1.6026x over previous
#include <cuda_runtime.h>
#include <cuda_fp16.h>
#include <cstdint>

#define D 128
#define MAX_N 100000
#define MAX_E 3200000
#define BINSZ 96              // fixed per-node bucket (deg ~ Poisson(32); 96 = +11 sigma)
#define MAX_SPILL 2048
#define BM 32                 // rows per group
#define GROUPS 8              // row-groups per block (256 rows/block)

// ---------------------------------------------------------------------------
// Static device scratch
// ---------------------------------------------------------------------------
__device__ int    g_is64;
__device__ int    g_cnt [MAX_N];                   // atomic degree counters
__device__ int    g_bins[(size_t)MAX_N * BINSZ];   // src ids, fixed stride
__device__ int    g_spillcnt;
__device__ int2   g_spill[MAX_SPILL];              // (src, dst) overflow edges
__device__ float  g_dis [MAX_N];                   // (deg+1)^-1/2
__device__ __half g_wh  [D * D];                   // W fp16
__device__ __half g_hp  [(size_t)MAX_N * D];       // x @ W^T (UNSCALED), fp16

// ---------------------------------------------------------------------------
// 1. prep: zero counters + detect edge dtype + convert W to fp16
// ---------------------------------------------------------------------------
__global__ void prep_kernel(const float* __restrict__ w, const int* __restrict__ p, int n) {
    int gid = blockIdx.x * blockDim.x + threadIdx.x;
    if (gid < n) g_cnt[gid] = 0;
    if (gid == 0) g_spillcnt = 0;
    if (gid < D * D / 2) {
        float2 v = ((const float2*)w)[gid];
        ((__half2*)g_wh)[gid] = __floats2half2_rn(v.x, v.y);
    }
    if (blockIdx.x == 0) {
        __shared__ int any;
        if (threadIdx.x == 0) any = 0;
        __syncthreads();
        int v = 0;
        for (int i = threadIdx.x; i < 2048; i += blockDim.x) v |= p[2 * i + 1];
        if (v) atomicOr(&any, 1);
        __syncthreads();
        if (threadIdx.x == 0) g_is64 = (any == 0) ? 1 : 0;
    }
}

// ---------------------------------------------------------------------------
// 2. fill: single edge pass builds binned adjacency + degree counts
// ---------------------------------------------------------------------------
__device__ __forceinline__ void fill_one(int s, int d, int n) {
    if ((unsigned)d < (unsigned)n) {
        if ((unsigned)s >= (unsigned)n) s = 0;
        int pos = atomicAdd(&g_cnt[d], 1);
        if (pos < BINSZ) {
            g_bins[(size_t)d * BINSZ + pos] = s;
        } else {
            int sp = atomicAdd(&g_spillcnt, 1);
            if (sp < MAX_SPILL) g_spill[sp] = make_int2(s, d);
        }
    }
}

__global__ void fill_kernel(const int* __restrict__ p, int e, int n) {
    int gid = blockIdx.x * blockDim.x + threadIdx.x;
    int stride = gridDim.x * blockDim.x;
    if (!g_is64) {
        const int4* s4 = (const int4*)p;
        const int4* d4 = (const int4*)(p + e);
        int e4 = e >> 2;
        for (int i = gid; i < e4; i += stride) {
            int4 sv = s4[i];
            int4 dv = d4[i];
            fill_one(sv.x, dv.x, n);
            fill_one(sv.y, dv.y, n);
            fill_one(sv.z, dv.z, n);
            fill_one(sv.w, dv.w, n);
        }
        if (gid < (e & 3)) {
            int i = (e & ~3) + gid;
            fill_one(p[i], p[(size_t)e + i], n);
        }
    } else {
        for (int i = gid; i < e; i += stride) {
            int s = p[2 * (size_t)i];
            int d = p[2 * ((size_t)e + i)];
            fill_one(s, d, n);
        }
    }
}

// ---------------------------------------------------------------------------
// 3. dis = rsqrt(deg + 1)
// ---------------------------------------------------------------------------
__global__ void dis_kernel(int n) {
    int i = blockIdx.x * blockDim.x + threadIdx.x;
    if (i < n) g_dis[i] = rsqrtf((float)(g_cnt[i] + 1));
}

// ---------------------------------------------------------------------------
// 4. tensor-core GEMM (round-13 structure, NO dis scaling):
//    g_hp[r][c] = half( x[r]·w[c] ). B-in-regs + persistent row groups,
//    double-buffered smem A staging. Depends only on prep (runs on stream2).
// ---------------------------------------------------------------------------
__global__ __launch_bounds__(256, 2) void gemm_mma_kernel(
    const float* __restrict__ x, int n)
{
    __shared__ __half sw[D][136];          // W staged once per block
    __shared__ __half sx[2][BM][136];      // double-buffered x tiles

    const int t = threadIdx.x;
    const int wid = t >> 5, lane = t & 31;
    const int blockRow0 = blockIdx.x * (BM * GROUPS);

    // stage W
    {
        int r = t >> 1, cseg = (t & 1) * 64;
        const uint4* wp = (const uint4*)(g_wh + r * D + cseg);
#pragma unroll
        for (int q = 0; q < 8; q++)
            *(uint4*)&sw[r][cseg + 8 * q] = wp[q];
    }
    __syncthreads();

    const int mrow0 = (wid & 1) * 16;
    const int ncol0 = (wid >> 1) * 32;
    const int brow = lane & 7;
    const int bcol = ((lane >> 3) & 1) * 8;
    const int arow = mrow0 + (lane & 15);
    const int acol = (lane >> 4) * 8;

    // B fragments resident: 8 k-chunks x 4 n-tiles x 2 regs
    uint32_t bf[8][4][2];
#pragma unroll
    for (int k0 = 0; k0 < 8; k0++) {
#pragma unroll
        for (int nt = 0; nt < 4; nt++) {
            unsigned baddr = (unsigned)__cvta_generic_to_shared(
                &sw[ncol0 + nt * 8 + brow][k0 * 16 + bcol]);
            asm volatile("ldmatrix.sync.aligned.m8n8.x2.shared.b16 {%0,%1}, [%2];"
                         : "=r"(bf[k0][nt][0]), "=r"(bf[k0][nt][1]) : "r"(baddr));
        }
    }

    const int sr = t >> 3, scseg = (t & 7) * 16;

    // prologue: load group 0
    float4 xv[4];
    {
        int gr = blockRow0 + sr;
        const float4* xp = (const float4*)(x + (size_t)gr * D + scseg);
#pragma unroll
        for (int q = 0; q < 4; q++)
            xv[q] = (gr < n) ? xp[q] : make_float4(0.f, 0.f, 0.f, 0.f);
    }

    __half2* hp2 = (__half2*)g_hp;

    for (int g = 0; g < GROUPS; g++) {
        const int buf = g & 1;
        const int row0 = blockRow0 + g * BM;
        if (row0 >= n) break;

#pragma unroll
        for (int q = 0; q < 4; q++) {
            *(__half2*)&sx[buf][sr][scseg + 4 * q]     = __floats2half2_rn(xv[q].x, xv[q].y);
            *(__half2*)&sx[buf][sr][scseg + 4 * q + 2] = __floats2half2_rn(xv[q].z, xv[q].w);
        }
        __syncthreads();

        if (g + 1 < GROUPS) {
            int gr = blockRow0 + (g + 1) * BM + sr;
            const float4* xp = (const float4*)(x + (size_t)gr * D + scseg);
#pragma unroll
            for (int q = 0; q < 4; q++)
                xv[q] = (gr < n) ? xp[q] : make_float4(0.f, 0.f, 0.f, 0.f);
        }

        float acc[4][4];
#pragma unroll
        for (int i = 0; i < 4; i++) { acc[i][0]=0.f; acc[i][1]=0.f; acc[i][2]=0.f; acc[i][3]=0.f; }

#pragma unroll
        for (int k0 = 0; k0 < 8; k0++) {
            unsigned aaddr = (unsigned)__cvta_generic_to_shared(
                &sx[buf][arow][k0 * 16 + acol]);
            uint32_t a0, a1, a2, a3;
            asm volatile("ldmatrix.sync.aligned.m8n8.x4.shared.b16 {%0,%1,%2,%3}, [%4];"
                         : "=r"(a0), "=r"(a1), "=r"(a2), "=r"(a3) : "r"(aaddr));
#pragma unroll
            for (int nt = 0; nt < 4; nt++) {
                asm volatile("mma.sync.aligned.m16n8k16.row.col.f32.f16.f16.f32 "
                             "{%0,%1,%2,%3}, {%4,%5,%6,%7}, {%8,%9}, {%0,%1,%2,%3};"
                             : "+f"(acc[nt][0]), "+f"(acc[nt][1]),
                               "+f"(acc[nt][2]), "+f"(acc[nt][3])
                             : "r"(a0), "r"(a1), "r"(a2), "r"(a3),
                               "r"(bf[k0][nt][0]), "r"(bf[k0][nt][1]));
            }
        }

        // epilogue: UNSCALED fp16 store
        const int gq = lane >> 2, tid4 = lane & 3;
        const int r0 = row0 + mrow0 + gq;
        const int r1 = r0 + 8;
#pragma unroll
        for (int nt = 0; nt < 4; nt++) {
            int c = ncol0 + nt * 8 + 2 * tid4;
            if (r0 < n) hp2[(size_t)r0 * 64 + (c >> 1)] = __floats2half2_rn(acc[nt][0], acc[nt][1]);
            if (r1 < n) hp2[(size_t)r1 * 64 + (c >> 1)] = __floats2half2_rn(acc[nt][2], acc[nt][3]);
        }
    }
}

// ---------------------------------------------------------------------------
// 5. gather-aggregate: one warp per node, two edges per iteration.
//    out[d] = dis[d] * ( dis[d]*h[d] + sum_s dis[s]*h[s] ) + bias
// ---------------------------------------------------------------------------
__device__ __forceinline__ void fma8(float* a, float sc, uint4 v) {
    float2 f;
    f = __half22float2(*(__half2*)&v.x); a[0] = fmaf(sc, f.x, a[0]); a[1] = fmaf(sc, f.y, a[1]);
    f = __half22float2(*(__half2*)&v.y); a[2] = fmaf(sc, f.x, a[2]); a[3] = fmaf(sc, f.y, a[3]);
    f = __half22float2(*(__half2*)&v.z); a[4] = fmaf(sc, f.x, a[4]); a[5] = fmaf(sc, f.y, a[5]);
    f = __half22float2(*(__half2*)&v.w); a[6] = fmaf(sc, f.x, a[6]); a[7] = fmaf(sc, f.y, a[7]);
}

__global__ __launch_bounds__(256) void aggregate_kernel(
    const float* __restrict__ bias, float* __restrict__ out, int n)
{
    int node = (blockIdx.x * blockDim.x + threadIdx.x) >> 5;
    int lane = threadIdx.x & 31;
    if (node >= n) return;
    const int half_id = lane >> 4;
    const int sub = lane & 15;

    const uint4* hp16 = (const uint4*)g_hp;
    const int start = node * BINSZ;
    int k = g_cnt[node];
    if (k > BINSZ) k = BINSZ;
    const float sdn = g_dis[node];

    float acc[8] = {0.f, 0.f, 0.f, 0.f, 0.f, 0.f, 0.f, 0.f};
    if (half_id == 0) fma8(acc, sdn, hp16[(size_t)node * 16 + sub]);   // self loop

    int j = 0;
    int full = k & ~31;
    for (; j < full; j += 32) {
        int my = g_bins[start + j + lane];
        float mydis = g_dis[my];
#pragma unroll
        for (int t2 = 0; t2 < 16; t2++) {
            int s  = __shfl_sync(0xFFFFFFFFu, my, 2 * t2 + half_id);
            float ds = __shfl_sync(0xFFFFFFFFu, mydis, 2 * t2 + half_id);
            fma8(acc, ds, hp16[(size_t)s * 16 + sub]);
        }
    }
    int m = k - j;
    if (m > 0) {
        int idx = j + lane;
        int my = (idx < k) ? g_bins[start + idx] : 0;
        float mydis = g_dis[my];
        int pairs = m >> 1;
        for (int t2 = 0; t2 < pairs; t2++) {
            int s  = __shfl_sync(0xFFFFFFFFu, my, 2 * t2 + half_id);
            float ds = __shfl_sync(0xFFFFFFFFu, mydis, 2 * t2 + half_id);
            fma8(acc, ds, hp16[(size_t)s * 16 + sub]);
        }
        if (m & 1) {
            int s  = __shfl_sync(0xFFFFFFFFu, my, m - 1);
            float ds = __shfl_sync(0xFFFFFFFFu, mydis, m - 1);
            if (half_id == 0) fma8(acc, ds, hp16[(size_t)s * 16 + sub]);
        }
    }

#pragma unroll
    for (int i = 0; i < 8; i++)
        acc[i] += __shfl_down_sync(0xFFFFFFFFu, acc[i], 16);

    if (half_id == 0) {
        const float4* b4 = (const float4*)bias;
        float4 ba = b4[sub * 2], bb = b4[sub * 2 + 1];
        float4 o0, o1;
        o0.x = fmaf(sdn, acc[0], ba.x);
        o0.y = fmaf(sdn, acc[1], ba.y);
        o0.z = fmaf(sdn, acc[2], ba.z);
        o0.w = fmaf(sdn, acc[3], ba.w);
        o1.x = fmaf(sdn, acc[4], bb.x);
        o1.y = fmaf(sdn, acc[5], bb.y);
        o1.z = fmaf(sdn, acc[6], bb.z);
        o1.w = fmaf(sdn, acc[7], bb.w);
        float4* op = (float4*)out + (size_t)node * 32 + sub * 2;
        op[0] = o0;
        op[1] = o1;
    }
}

// ---------------------------------------------------------------------------
// 6. spill fixup (normally zero work): out[d] += dis[d]*dis[s]*h[s]
// ---------------------------------------------------------------------------
__global__ void spill_kernel(float* __restrict__ out) {
    int nsp = g_spillcnt;
    if (nsp > MAX_SPILL) nsp = MAX_SPILL;
    int warp = (blockIdx.x * blockDim.x + threadIdx.x) >> 5;
    int lane = threadIdx.x & 31;
    int wstride = (gridDim.x * blockDim.x) >> 5;
    for (int i = warp; i < nsp; i += wstride) {
        int2 ed = g_spill[i];
        float sd = g_dis[ed.y] * g_dis[ed.x];
        uint2 v = ((const uint2*)g_hp)[(size_t)ed.x * 32 + lane];
        float2 f0 = __half22float2(*(__half2*)&v.x);
        float2 f1 = __half22float2(*(__half2*)&v.y);
        float* o = out + (size_t)ed.y * D + lane * 4;
        atomicAdd(o + 0, sd * f0.x);
        atomicAdd(o + 1, sd * f0.y);
        atomicAdd(o + 2, sd * f1.x);
        atomicAdd(o + 3, sd * f1.y);
    }
}

// ---------------------------------------------------------------------------
// 7. zero any padding tail of d_out
// ---------------------------------------------------------------------------
__global__ void zero_tail_kernel(float* out, int begin, int end) {
    int i = begin + blockIdx.x * blockDim.x + threadIdx.x;
    if (i < end) out[i] = 0.f;
}

// ---------------------------------------------------------------------------
extern "C" void kernel_launch(void* const* d_in, const int* in_sizes, int n_in,
                              void* d_out, int out_size) {
    const float* x    = (const float*)d_in[0];
    const int*   ei   = (const int*)d_in[1];
    const float* w    = (const float*)d_in[2];
    const float* bias = (const float*)d_in[3];
    float*       out  = (float*)d_out;

    const int n = in_sizes[0] / D;     // 100000
    const int e = in_sizes[1] / 2;     // 3200000

    // Side stream + events, created once on the (uncaptured) correctness call.
    static cudaStream_t s2 = nullptr;
    static cudaEvent_t evA = nullptr, evB = nullptr;
    if (s2 == nullptr) {
        cudaStreamCreateWithFlags(&s2, cudaStreamNonBlocking);
        cudaEventCreateWithFlags(&evA, cudaEventDisableTiming);
        cudaEventCreateWithFlags(&evB, cudaEventDisableTiming);
    }

    // 1. prep (stream 0)
    prep_kernel<<<(n + 255) / 256, 256>>>(w, ei, n);
    cudaEventRecord(evA, 0);

    // 2a. GEMM on side stream (depends only on prep: unscaled h)
    cudaStreamWaitEvent(s2, evA, 0);
    {
        int rows_per_block = BM * GROUPS;
        gemm_mma_kernel<<<(n + rows_per_block - 1) / rows_per_block, 256, 0, s2>>>(x, n);
    }
    cudaEventRecord(evB, s2);

    // 2b. fill + dis on stream 0 (overlaps with GEMM)
    fill_kernel<<<2048, 256>>>(ei, e, n);
    dis_kernel<<<(n + 255) / 256, 256>>>(n);

    // join: aggregate needs both
    cudaStreamWaitEvent(0, evB, 0);

    // 3. gather aggregation with fused per-src norm + finalize
    {
        long long total_threads = (long long)n * 32;
        int blocks = (int)((total_threads + 255) / 256);
        aggregate_kernel<<<blocks, 256>>>(bias, out, n);
    }

    // 4. spill fixup (no-op unless a node exceeded BINSZ)
    spill_kernel<<<64, 256>>>(out);

    // 5. padding tail, if any
    if (out_size > n * D) {
        int extra = out_size - n * D;
        zero_tail_kernel<<<(extra + 255) / 256, 256>>>(out, n * D, out_size);
    }
}